// round 9
// baseline (speedup 1.0000x reference)
#include <cuda_runtime.h>
#include <cuda_bf16.h>

#define B_SZ 32
#define F_SZ 257
#define T_SZ 3000
#define T4_SZ 750                 // float4 per row
#define NCHUNK 8
#define FCHUNK 33                 // 7*33 = 231, last chunk = 26 rows
#define NXT 3                     // t4 tiles of 256
#define THREADS 256
#define NB1 (NXT * NCHUNK * B_SZ) // 768 colsum blocks
#define NFG 65                    // f-groups of 4 rows
#define NB3 (NXT * NFG * B_SZ)    // 6240 normalize blocks
#define MOMENTUM 0.99f
#define ONE_MINUS_M 0.01f
#define EPS 1e-8f
#define SEG 12                    // 256*12 = 3072 >= 3000

// Scratch (static device globals; zero-initialized at load)
__device__ __align__(16) float g_part[NCHUNK * B_SZ * T_SZ];
__device__ __align__(16) float g_inv[B_SZ * T_SZ];
__device__ int g_cnt1[B_SZ];      // k1-block arrivals per batch (self-reset)
__device__ int g_flag[B_SZ];      // scan-done flag per batch (self-reset)
__device__ int g_cnt3[B_SZ];      // k3-block arrivals per batch (self-reset)

__global__ __launch_bounds__(THREADS)
void ema_all(const float* __restrict__ mag,
             const float* __restrict__ bias,
             const float* __restrict__ running_mean,
             float* __restrict__ out_norm,
             float* __restrict__ out_mean) {
    __shared__ float s_buf[2 * T_SZ];
    __shared__ float sA[THREADS], sB[THREADS];
    __shared__ int s_last;

    const int bid = blockIdx.x;
    const int tid = threadIdx.x;

    if (bid < NB1) {
        // ================= k1 role: column sums ==========================
        const int b   = bid / (NXT * NCHUNK);          // slowest: batch
        const int rem = bid % (NXT * NCHUNK);
        const int ch  = rem / NXT;
        const int xt  = rem % NXT;
        const int t4  = xt * THREADS + tid;

        if (t4 < T4_SZ) {
            int f0 = ch * FCHUNK;
            int f1 = f0 + FCHUNK;
            if (f1 > F_SZ) f1 = F_SZ;

            const float4* base = reinterpret_cast<const float4*>(mag)
                               + (size_t)b * F_SZ * T4_SZ + t4;

            float4 s = make_float4(0.f, 0.f, 0.f, 0.f);
            int f = f0;
            #pragma unroll 1
            for (; f + 8 <= f1; f += 8) {
                float4 v0 = base[(size_t)(f + 0) * T4_SZ];
                float4 v1 = base[(size_t)(f + 1) * T4_SZ];
                float4 v2 = base[(size_t)(f + 2) * T4_SZ];
                float4 v3 = base[(size_t)(f + 3) * T4_SZ];
                float4 v4 = base[(size_t)(f + 4) * T4_SZ];
                float4 v5 = base[(size_t)(f + 5) * T4_SZ];
                float4 v6 = base[(size_t)(f + 6) * T4_SZ];
                float4 v7 = base[(size_t)(f + 7) * T4_SZ];
                s.x += ((v0.x + v1.x) + (v2.x + v3.x)) + ((v4.x + v5.x) + (v6.x + v7.x));
                s.y += ((v0.y + v1.y) + (v2.y + v3.y)) + ((v4.y + v5.y) + (v6.y + v7.y));
                s.z += ((v0.z + v1.z) + (v2.z + v3.z)) + ((v4.z + v5.z) + (v6.z + v7.z));
                s.w += ((v0.w + v1.w) + (v2.w + v3.w)) + ((v4.w + v5.w) + (v6.w + v7.w));
            }
            for (; f < f1; f++) {
                float4 v = base[(size_t)f * T4_SZ];
                s.x += v.x; s.y += v.y; s.z += v.z; s.w += v.w;
            }
            reinterpret_cast<float4*>(g_part)[((size_t)ch * B_SZ + b) * T4_SZ + t4] = s;
        }

        __threadfence();            // release partial writes
        __syncthreads();
        if (tid == 0)
            s_last = (atomicAdd(&g_cnt1[b], 1) == NXT * NCHUNK - 1);
        __syncthreads();
        if (!s_last) return;

        // ---- last block of batch b: reduce partials + full EMA scan ------
        for (int t = tid; t < T_SZ; t += THREADS) {
            float acc = 0.f;
            #pragma unroll
            for (int c = 0; c < NCHUNK; c++)
                acc += __ldcg(&g_part[((size_t)c * B_SZ + b) * T_SZ + t]);
            s_buf[t] = acc * (1.0f / (float)F_SZ);
        }
        __syncthreads();

        float x[SEG];
        float A = 1.0f, Bc = 0.0f;
        const int t0 = tid * SEG;
        #pragma unroll
        for (int j = 0; j < SEG; j++) {
            int t = t0 + j;
            if (t < T_SZ) {
                float fm = s_buf[t];
                x[j] = fm;
                A  *= MOMENTUM;
                Bc  = MOMENTUM * Bc + ONE_MINUS_M * fm;
            }
        }
        __syncthreads();

        sA[tid] = A; sB[tid] = Bc;
        __syncthreads();
        #pragma unroll
        for (int off = 1; off < THREADS; off <<= 1) {
            float a2 = sA[tid], b2 = sB[tid];
            float a1 = 1.0f, b1 = 0.0f;
            if (tid >= off) { a1 = sA[tid - off]; b1 = sB[tid - off]; }
            __syncthreads();
            sA[tid] = a2 * a1;
            sB[tid] = a2 * b1 + b2;
            __syncthreads();
        }

        float Ap = 1.0f, Bp = 0.0f;
        if (tid > 0) { Ap = sA[tid - 1]; Bp = sB[tid - 1]; }

        float m = Ap * running_mean[0] + Bp;
        const float bi = bias[0];

        #pragma unroll
        for (int j = 0; j < SEG; j++) {
            int t = t0 + j;
            if (t < T_SZ) {
                m = MOMENTUM * m + ONE_MINUS_M * x[j];
                float mwb = m + bi;
                s_buf[t]        = 1.0f / (mwb + EPS);
                s_buf[T_SZ + t] = mwb;
            }
        }
        __syncthreads();

        float* invp  = g_inv + (size_t)b * T_SZ;
        float* meanp = out_mean + (size_t)b * T_SZ;
        for (int t = tid; t < T_SZ; t += THREADS) {
            invp[t]  = s_buf[t];
            meanp[t] = s_buf[T_SZ + t];
        }
        __threadfence();            // release inv/mean
        __syncthreads();
        if (tid == 0) {
            atomicExch(&g_cnt1[b], 0);       // replay-safe reset
            atomicExch(&g_flag[b], 1);       // publish
        }
    } else {
        // ================= k3 role: normalize =============================
        const int nid = bid - NB1;
        const int b   = nid / (NXT * NFG);             // slowest: batch
        const int rem = nid % (NXT * NFG);
        const int fg  = rem / NXT;
        const int xt  = rem % NXT;
        const int t4  = xt * THREADS + tid;
        const int f0  = fg * 4;

        // wait for this batch's inv
        if (tid == 0) {
            while (atomicAdd(&g_flag[b], 0) == 0) __nanosleep(128);
            int v = atomicAdd(&g_cnt3[b], 1);
            if (v == NXT * NFG - 1) {                  // last consumer: reset
                atomicExch(&g_flag[b], 0);
                atomicExch(&g_cnt3[b], 0);
            }
        }
        __syncthreads();
        __threadfence();            // acquire

        if (t4 >= T4_SZ) return;

        float4 iv;
        {
            const float4* ip = reinterpret_cast<const float4*>(g_inv)
                             + (size_t)b * T4_SZ + t4;
            iv = __ldcg(ip);
        }

        const int nrows = (F_SZ - f0) < 4 ? (F_SZ - f0) : 4;
        size_t idx0 = ((size_t)b * F_SZ + f0) * T4_SZ + t4;

        float4 v[4];
        #pragma unroll
        for (int r = 0; r < 4; r++)
            if (r < nrows) v[r] = reinterpret_cast<const float4*>(mag)[idx0 + (size_t)r * T4_SZ];

        #pragma unroll
        for (int r = 0; r < 4; r++) {
            if (r < nrows) {
                v[r].x *= iv.x; v[r].y *= iv.y; v[r].z *= iv.z; v[r].w *= iv.w;
                __stcs(reinterpret_cast<float4*>(out_norm) + idx0 + (size_t)r * T4_SZ, v[r]);
            }
        }
    }
}

// ---------------------------------------------------------------------------
extern "C" void kernel_launch(void* const* d_in, const int* in_sizes, int n_in,
                              void* d_out, int out_size) {
    const float* mag          = (const float*)d_in[0];
    const float* bias         = (const float*)d_in[1];
    const float* running_mean = (const float*)d_in[2];
    float* out = (float*)d_out;

    float* out_norm = out;                                // [B, F, T]
    float* out_mean = out + (size_t)B_SZ * F_SZ * T_SZ;   // [B, 1, T]

    ema_all<<<NB1 + NB3, THREADS>>>(mag, bias, running_mean, out_norm, out_mean);
}

// round 11
// speedup vs baseline: 1.0453x; 1.0453x over previous
#include <cuda_runtime.h>
#include <cuda_bf16.h>

#define B_SZ 32
#define F_SZ 257
#define T_SZ 3000
#define T4_SZ 750                 // float4 per row
#define NCHUNK 8
#define FCHUNK 33                 // 7*33 = 231, last chunk = 26 rows
#define NXT 3                     // t4 tiles of 256
#define THREADS 256
#define NB1 (NXT * NCHUNK * B_SZ) // 768 colsum blocks
#define MOMENTUM 0.99f
#define ONE_MINUS_M 0.01f
#define EPS 1e-8f
#define SEG 12                    // 256*12 = 3072 >= 3000

// Scratch (static device globals; zero-initialized at load)
__device__ __align__(16) float g_part[NCHUNK * B_SZ * T_SZ];
__device__ __align__(16) float g_inv[B_SZ * T_SZ];
__device__ int g_cnt1[B_SZ];      // k1-block arrivals per batch (self-reset)

// ---------------------------------------------------------------------------
// kA: column sums; last-arriving block per batch folds reduce + EMA scan.
// grid: 768 blocks (b-major slowest), 256 threads.
// ---------------------------------------------------------------------------
__global__ __launch_bounds__(THREADS)
void ema_kA(const float* __restrict__ mag,
            const float* __restrict__ bias,
            const float* __restrict__ running_mean,
            float* __restrict__ out_mean) {
    __shared__ float s_buf[2 * T_SZ];
    __shared__ float sA[THREADS], sB[THREADS];
    __shared__ int s_last;

    const int bid = blockIdx.x;
    const int tid = threadIdx.x;
    const int b   = bid / (NXT * NCHUNK);          // slowest: batch
    const int rem = bid % (NXT * NCHUNK);
    const int ch  = rem / NXT;
    const int xt  = rem % NXT;
    const int t4  = xt * THREADS + tid;

    if (t4 < T4_SZ) {
        int f0 = ch * FCHUNK;
        int f1 = f0 + FCHUNK;
        if (f1 > F_SZ) f1 = F_SZ;

        const float4* base = reinterpret_cast<const float4*>(mag)
                           + (size_t)b * F_SZ * T4_SZ + t4;

        float4 s = make_float4(0.f, 0.f, 0.f, 0.f);
        int f = f0;
        #pragma unroll 1
        for (; f + 8 <= f1; f += 8) {
            float4 v0 = base[(size_t)(f + 0) * T4_SZ];
            float4 v1 = base[(size_t)(f + 1) * T4_SZ];
            float4 v2 = base[(size_t)(f + 2) * T4_SZ];
            float4 v3 = base[(size_t)(f + 3) * T4_SZ];
            float4 v4 = base[(size_t)(f + 4) * T4_SZ];
            float4 v5 = base[(size_t)(f + 5) * T4_SZ];
            float4 v6 = base[(size_t)(f + 6) * T4_SZ];
            float4 v7 = base[(size_t)(f + 7) * T4_SZ];
            s.x += ((v0.x + v1.x) + (v2.x + v3.x)) + ((v4.x + v5.x) + (v6.x + v7.x));
            s.y += ((v0.y + v1.y) + (v2.y + v3.y)) + ((v4.y + v5.y) + (v6.y + v7.y));
            s.z += ((v0.z + v1.z) + (v2.z + v3.z)) + ((v4.z + v5.z) + (v6.z + v7.z));
            s.w += ((v0.w + v1.w) + (v2.w + v3.w)) + ((v4.w + v5.w) + (v6.w + v7.w));
        }
        for (; f < f1; f++) {
            float4 v = base[(size_t)f * T4_SZ];
            s.x += v.x; s.y += v.y; s.z += v.z; s.w += v.w;
        }
        reinterpret_cast<float4*>(g_part)[((size_t)ch * B_SZ + b) * T4_SZ + t4] = s;
    }

    __threadfence();            // release partial writes
    __syncthreads();
    if (tid == 0)
        s_last = (atomicAdd(&g_cnt1[b], 1) == NXT * NCHUNK - 1);
    __syncthreads();
    if (!s_last) return;

    // ---- last block of batch b: reduce partials + full EMA scan ----------
    for (int t = tid; t < T_SZ; t += THREADS) {
        float acc = 0.f;
        #pragma unroll
        for (int c = 0; c < NCHUNK; c++)
            acc += __ldcg(&g_part[((size_t)c * B_SZ + b) * T_SZ + t]);
        s_buf[t] = acc * (1.0f / (float)F_SZ);
    }
    __syncthreads();

    float x[SEG];
    float A = 1.0f, Bc = 0.0f;
    const int t0 = tid * SEG;
    #pragma unroll
    for (int j = 0; j < SEG; j++) {
        int t = t0 + j;
        if (t < T_SZ) {
            float fm = s_buf[t];
            x[j] = fm;
            A  *= MOMENTUM;
            Bc  = MOMENTUM * Bc + ONE_MINUS_M * fm;
        }
    }
    __syncthreads();

    sA[tid] = A; sB[tid] = Bc;
    __syncthreads();
    #pragma unroll
    for (int off = 1; off < THREADS; off <<= 1) {
        float a2 = sA[tid], b2 = sB[tid];
        float a1 = 1.0f, b1 = 0.0f;
        if (tid >= off) { a1 = sA[tid - off]; b1 = sB[tid - off]; }
        __syncthreads();
        sA[tid] = a2 * a1;
        sB[tid] = a2 * b1 + b2;
        __syncthreads();
    }

    float Ap = 1.0f, Bp = 0.0f;
    if (tid > 0) { Ap = sA[tid - 1]; Bp = sB[tid - 1]; }

    float m = Ap * running_mean[0] + Bp;
    const float bi = bias[0];

    #pragma unroll
    for (int j = 0; j < SEG; j++) {
        int t = t0 + j;
        if (t < T_SZ) {
            m = MOMENTUM * m + ONE_MINUS_M * x[j];
            float mwb = m + bi;
            s_buf[t]        = 1.0f / (mwb + EPS);
            s_buf[T_SZ + t] = mwb;
        }
    }
    __syncthreads();

    float* invp  = g_inv + (size_t)b * T_SZ;
    float* meanp = out_mean + (size_t)b * T_SZ;
    for (int t = tid; t < T_SZ; t += THREADS) {
        invp[t]  = s_buf[t];
        meanp[t] = s_buf[T_SZ + t];
    }
    __syncthreads();
    if (tid == 0) atomicExch(&g_cnt1[b], 0);   // replay-safe reset
}

// ---------------------------------------------------------------------------
// kB: mag_norm = mag * inv[b,t]; 4 f-rows per iv load; reverse-b for L2
// freshness.  grid: (3, 65, 32), block 256.
// ---------------------------------------------------------------------------
__global__ __launch_bounds__(256)
void ema_kB(const float* __restrict__ mag,
            float* __restrict__ out_norm) {
    int t4 = blockIdx.x * blockDim.x + threadIdx.x;
    if (t4 >= T4_SZ) return;
    int f0 = blockIdx.y * 4;                 // 0,4,...,256
    int b  = (B_SZ - 1) - blockIdx.z;

    float4 iv = __ldca(reinterpret_cast<const float4*>(g_inv) + (size_t)b * T4_SZ + t4);

    const int nrows = (F_SZ - f0) < 4 ? (F_SZ - f0) : 4;
    size_t idx0 = ((size_t)b * F_SZ + f0) * T4_SZ + t4;

    float4 v[4];
    #pragma unroll
    for (int r = 0; r < 4; r++)
        if (r < nrows) v[r] = reinterpret_cast<const float4*>(mag)[idx0 + (size_t)r * T4_SZ];

    #pragma unroll
    for (int r = 0; r < 4; r++) {
        if (r < nrows) {
            v[r].x *= iv.x; v[r].y *= iv.y; v[r].z *= iv.z; v[r].w *= iv.w;
            __stcs(reinterpret_cast<float4*>(out_norm) + idx0 + (size_t)r * T4_SZ, v[r]);
        }
    }
}

// ---------------------------------------------------------------------------
extern "C" void kernel_launch(void* const* d_in, const int* in_sizes, int n_in,
                              void* d_out, int out_size) {
    const float* mag          = (const float*)d_in[0];
    const float* bias         = (const float*)d_in[1];
    const float* running_mean = (const float*)d_in[2];
    float* out = (float*)d_out;

    float* out_norm = out;                                // [B, F, T]
    float* out_mean = out + (size_t)B_SZ * F_SZ * T_SZ;   // [B, 1, T]

    ema_kA<<<NB1, THREADS>>>(mag, bias, running_mean, out_mean);
    {
        dim3 grid(3, (F_SZ + 3) / 4, B_SZ);
        ema_kB<<<grid, 256>>>(mag, out_norm);
    }
}